// round 3
// baseline (speedup 1.0000x reference)
#include <cuda_runtime.h>
#include <math.h>

// Problem constants
#define NIMG   4
#define HW     48
#define CH     3
#define PLANE  (HW*HW)            // 2304
#define NPIX   (PLANE*CH)         // 6912 per image
#define KS     21
#define KR     10

// Config
#define TPTS   257                // tanh-mean table points on [0,1]
#define GRID   144                // 1 block/SM guaranteed (<=148) -> safe spin barrier
#define TB     256
#define YT     4                  // output rows per conv tile (144 = 4n*3c*12 ytiles)
#define TROWS  (YT + KS - 1)      // 24
#define TCOLS  (HW + KS - 1)      // 68

// Scratch (device globals; no allocation)
__device__ float d_F[NIMG * NPIX];        // exp(-2*G(inputs)), planar [n][c][y][x]
__device__ float d_table[NIMG * TPTS];
__device__ unsigned g_cnt = 0;
__device__ volatile unsigned g_gen = 0;

// Shared pool layout (floats):
//  P1:  IN @0 (1632), H @1700 (1152), KG @2900 (21)
//  P2:  F image @0 (6912)
//  P3:  IN @0 (1632), DF @1632 (1632), HM @3264 (1152), HW @4416 (1152),
//       KM @5568 (21), KW @5600 (21), TBL @5632 (257)
#define SP_IN   0
#define SP_H    1700
#define SP_KG   2900
#define SP_DF   1632
#define SP_HM   3264
#define SP_HW   4416
#define SP_KM   5568
#define SP_KW   5600
#define SP_TBL  5632

__device__ __forceinline__ float frcp(float x) {
    float r;
    asm("rcp.approx.f32 %0, %1;" : "=f"(r) : "f"(x));
    return r;
}

// Grid-wide barrier (sense via monotonically increasing generation; safe
// across graph replays, all GRID blocks co-resident by construction).
__device__ __forceinline__ void gridbar() {
    __syncthreads();
    __threadfence();
    if (threadIdx.x == 0) {
        unsigned gen = g_gen;
        if (atomicAdd(&g_cnt, 1u) == GRID - 1) {
            g_cnt = 0;
            __threadfence();
            g_gen = gen + 1;
        } else {
            while (g_gen == gen) {}
        }
    }
    __syncthreads();
    __threadfence();
}

// One warp builds a unit-L2 1D Gaussian (the 2D kernel is exactly the outer
// product of this with itself: k2d/||k2d||_2 = g1 (x) g1).
__device__ __forceinline__ void make_k1d(float gamma, float* out) {
    int lane = threadIdx.x & 31;
    float inv2s2 = 0.5f * gamma * gamma;          // 1/(2 sigma^2), sigma=1/gamma
    const float step = (21.0f / 32.0f) / 20.0f;   // linspace(0, KS/FS, KS) step
    const float mean = 21.0f / 64.0f;             // KS/(2*FS)
    float v = 0.0f;
    if (lane < KS) {
        float d = (float)lane * step - mean;
        v = expf(-d * d * inv2s2);                // amp cancels in L2 norm
    }
    float ss = v * v;
    #pragma unroll
    for (int o = 16; o > 0; o >>= 1) ss += __shfl_xor_sync(0xffffffffu, ss, o);
    if (lane < KS) out[lane] = v * rsqrtf(ss);
}

__global__ __launch_bounds__(TB, 1)
void inrf_fused(const float* __restrict__ in,
                const float* __restrict__ gm,
                const float* __restrict__ gw,
                const float* __restrict__ gg,
                float* __restrict__ out) {
    __shared__ float sp[NPIX];   // 27648 B

    const int tid  = threadIdx.x;
    const int warp = tid >> 5;
    const int lane = tid & 31;

    // Conv-phase block decomposition: 144 = 4n * 3c * 12 ytiles
    const int b   = blockIdx.x;
    const int n   = b / 36;
    const int rem = b % 36;
    const int c   = rem / 12;
    const int y0  = (rem % 12) * YT;

    // ---------------- Phase 1: F = exp(-2 * G(inputs)), separable conv -----
    if (warp == 0) make_k1d(gg[c], sp + SP_KG);

    // zero-padded input tile (rows y0-10..y0+13, cols -10..57), channel c
    for (int i = tid; i < TROWS * TCOLS; i += TB) {
        int r  = i / TCOLS;
        int xc = i % TCOLS - KR;
        int yy = y0 - KR + r;
        float v = 0.0f;
        if ((unsigned)yy < HW && (unsigned)xc < HW)
            v = in[((n * HW + yy) * HW + xc) * CH + c];
        sp[SP_IN + i] = v;
    }
    __syncthreads();

    // horizontal pass
    for (int i = tid; i < TROWS * HW; i += TB) {
        int r = i / HW, x = i % HW;
        const float* row = sp + SP_IN + r * TCOLS + x;
        float s = 0.0f;
        #pragma unroll
        for (int k = 0; k < KS; k++) s = fmaf(row[k], sp[SP_KG + k], s);
        sp[SP_H + i] = s;
    }
    __syncthreads();

    // vertical pass -> F (planar layout for fast phase-2 streaming)
    for (int i = tid; i < YT * HW; i += TB) {
        int yo = i / HW, x = i % HW;
        float s = 0.0f;
        #pragma unroll
        for (int k = 0; k < KS; k++)
            s = fmaf(sp[SP_H + (yo + k) * HW + x], sp[SP_KG + k], s);
        d_F[(n * CH + c) * PLANE + (y0 + yo) * HW + x] = __expf(-2.0f * s);
    }

    gridbar();

    // ---------------- Phase 2: table[n][t] = mean_b tanh(x_t - b) ----------
    // tanh(x-b) = 1 - 2/(1 + e^{2x} e^{-2b});   F = e^{-2b} precomputed.
    {
        const int n2 = blockIdx.x & 3;                 // 36 blocks per image
        const int t  = (blockIdx.x >> 2) * 8 + warp;   // one table point per warp

        const float4* Fv  = (const float4*)(d_F + n2 * NPIX);
        float4*       spv = (float4*)sp;
        for (int i = tid; i < NPIX / 4; i += TB) spv[i] = Fv[i];
        __syncthreads();

        if (t < TPTS) {
            float E = __expf(2.0f * (float)t * (1.0f / (TPTS - 1)));
            float a0 = 0.f, a1 = 0.f, a2 = 0.f, a3 = 0.f;
            #pragma unroll 2
            for (int i = lane; i < NPIX; i += 128) {   // 54 exact iterations
                a0 += frcp(fmaf(E, sp[i],      1.0f));
                a1 += frcp(fmaf(E, sp[i + 32], 1.0f));
                a2 += frcp(fmaf(E, sp[i + 64], 1.0f));
                a3 += frcp(fmaf(E, sp[i + 96], 1.0f));
            }
            float s = (a0 + a1) + (a2 + a3);
            #pragma unroll
            for (int o = 16; o > 0; o >>= 1)
                s += __shfl_xor_sync(0xffffffffu, s, o);
            if (lane == 0)
                d_table[n2 * TPTS + t] = 1.0f - s * (2.0f / (float)NPIX);
        }
    }

    gridbar();

    // ---------------- Phase 3: out = M(inputs) - W(diff) -------------------
    if (warp == 0)      make_k1d(gm[c], sp + SP_KM);
    else if (warp == 1) make_k1d(gw[c], sp + SP_KW);

    for (int i = tid; i < TPTS; i += TB)
        sp[SP_TBL + i] = d_table[n * TPTS + i];
    __syncthreads();   // table visible before diff interp below

    // zero-padded (input, diff) tiles; diff = lerp of per-image table at x
    for (int i = tid; i < TROWS * TCOLS; i += TB) {
        int r  = i / TCOLS;
        int xc = i % TCOLS - KR;
        int yy = y0 - KR + r;
        float v = 0.0f, d = 0.0f;
        if ((unsigned)yy < HW && (unsigned)xc < HW) {
            v = in[((n * HW + yy) * HW + xc) * CH + c];
            float u = v * (float)(TPTS - 1);
            u = fminf(fmaxf(u, 0.0f), (float)(TPTS - 1) - 1e-3f);
            int   i0 = (int)u;
            float fr = u - (float)i0;
            float t0 = sp[SP_TBL + i0], t1 = sp[SP_TBL + i0 + 1];
            d = fmaf(t1 - t0, fr, t0);
        }
        sp[SP_IN + i] = v;
        sp[SP_DF + i] = d;
    }
    __syncthreads();

    // horizontal passes (both convs)
    for (int i = tid; i < TROWS * HW; i += TB) {
        int r = i / HW, x = i % HW;
        const float* rin = sp + SP_IN + r * TCOLS + x;
        const float* rdf = sp + SP_DF + r * TCOLS + x;
        float sm = 0.0f, sw = 0.0f;
        #pragma unroll
        for (int k = 0; k < KS; k++) {
            sm = fmaf(rin[k], sp[SP_KM + k], sm);
            sw = fmaf(rdf[k], sp[SP_KW + k], sw);
        }
        sp[SP_HM + i] = sm;
        sp[SP_HW + i] = sw;
    }
    __syncthreads();

    // vertical passes + final subtraction (L = 1)
    for (int i = tid; i < YT * HW; i += TB) {
        int yo = i / HW, x = i % HW;
        float sm = 0.0f, sw = 0.0f;
        #pragma unroll
        for (int k = 0; k < KS; k++) {
            sm = fmaf(sp[SP_HM + (yo + k) * HW + x], sp[SP_KM + k], sm);
            sw = fmaf(sp[SP_HW + (yo + k) * HW + x], sp[SP_KW + k], sw);
        }
        out[((n * HW + y0 + yo) * HW + x) * CH + c] = sm - sw;
    }
}

extern "C" void kernel_launch(void* const* d_in, const int* in_sizes, int n_in,
                              void* d_out, int out_size) {
    const float* in = (const float*)d_in[0];
    const float* gm = (const float*)d_in[1];
    const float* gw = (const float*)d_in[2];
    const float* gg = (const float*)d_in[3];
    float* out = (float*)d_out;

    inrf_fused<<<GRID, TB>>>(in, gm, gw, gg, out);
}

// round 4
// speedup vs baseline: 1.1068x; 1.1068x over previous
#include <cuda_runtime.h>
#include <math.h>

// Problem constants
#define NIMG   4
#define HW     48
#define CH     3
#define PLANE  (HW*HW)            // 2304
#define NPIX   (PLANE*CH)         // 6912 per image
#define KS     21
#define KR     10

// Config
#define TPTS   257                // x-grid: t/256, t=0..256
#define GRID   144                // 1 block/SM -> all co-resident, safe spin barrier
#define TB     512
#define YT     4                  // output rows per conv tile (144 = 4n*3c*12)
#define TROWS  (YT + KS - 1)      // 24
#define TCOLS  (HW + KS - 1)      // 68

// Histogram / tanh-table config (b-grid step = 1/256, aligned with x-grid)
#define BINS   5632               // blur in [0, ~21] -> j up to ~5377; headroom
#define OFFD   (BINS - 1)         // T index offset: d = t - j in [-(BINS-1), 256]
#define TSIZE  5904               // padded (staging may over-read the tail)
#define TSLICE 41                 // ceil(TSIZE / GRID)

// Scratch (device globals; no allocation). Zero-init by module load;
// d_W / d_jmin / d_jmax are re-armed in Phase 3 each run (graph-replay safe).
__device__ float d_W[NIMG * BINS];          // linear-binned blur histogram
__device__ int   d_jmin[NIMG] = {BINS, BINS, BINS, BINS};
__device__ int   d_jmax[NIMG] = {0, 0, 0, 0};
__device__ float d_T[TSIZE];                // tanh((i - OFFD)/256)
__device__ float d_table[NIMG * TPTS];      // per-image tanh-mean table
__device__ unsigned g_cnt = 0;
__device__ volatile unsigned g_gen = 0;

// Shared pool (floats):
//  P1: IN @0 (1632), H @1700 (1152), KG @2900 (21)
//  P2: W @0 (<=5632), T @5648 (<=5648)
//  P3: IN @0, DF @1632, HM @3264, HW @4416, KM @5568, KW @5600, TBL @5632
#define SP_IN   0
#define SP_H    1700
#define SP_KG   2900
#define SP2_W   0
#define SP2_T   5648
#define SP_DF   1632
#define SP_HM   3264
#define SP_HW   4416
#define SP_KM   5568
#define SP_KW   5600
#define SP_TBL  5632
#define POOL    11584             // 46336 B static smem

// Grid-wide barrier (monotone generation; all GRID blocks co-resident).
__device__ __forceinline__ void gridbar() {
    __syncthreads();
    __threadfence();
    if (threadIdx.x == 0) {
        unsigned gen = g_gen;
        if (atomicAdd(&g_cnt, 1u) == GRID - 1) {
            g_cnt = 0;
            __threadfence();
            g_gen = gen + 1;
        } else {
            while (g_gen == gen) {}
        }
    }
    __syncthreads();
    __threadfence();
}

// One warp builds a unit-L2 1D Gaussian (2D kernel = exact outer product).
__device__ __forceinline__ void make_k1d(float gamma, float* out) {
    int lane = threadIdx.x & 31;
    float inv2s2 = 0.5f * gamma * gamma;          // 1/(2 sigma^2), sigma=1/gamma
    const float step = (21.0f / 32.0f) / 20.0f;
    const float mean = 21.0f / 64.0f;
    float v = 0.0f;
    if (lane < KS) {
        float d = (float)lane * step - mean;
        v = expf(-d * d * inv2s2);
    }
    float ss = v * v;
    #pragma unroll
    for (int o = 16; o > 0; o >>= 1) ss += __shfl_xor_sync(0xffffffffu, ss, o);
    if (lane < KS) out[lane] = v * rsqrtf(ss);
}

__global__ __launch_bounds__(TB, 1)
void inrf_fused(const float* __restrict__ in,
                const float* __restrict__ gm,
                const float* __restrict__ gw,
                const float* __restrict__ gg,
                float* __restrict__ out) {
    __shared__ float sp[POOL];

    const int tid  = threadIdx.x;
    const int warp = tid >> 5;
    const int lane = tid & 31;

    // Conv-phase decomposition: 144 = 4n * 3c * 12 ytiles
    const int b   = blockIdx.x;
    const int n   = b / 36;
    const int rem = b % 36;
    const int c   = rem / 12;
    const int y0  = (rem % 12) * YT;

    // ---------------- Phase 1: blur = G(inputs); bin into histogram --------
    if (warp == 0) make_k1d(gg[c], sp + SP_KG);

    // global tanh lookup slice (image-independent): T[i] = tanh((i-OFFD)/256)
    {
        int i0 = b * TSLICE;
        for (int i = i0 + tid; i < i0 + TSLICE && i < TSIZE; i += TB)
            d_T[i] = tanhf((float)(i - OFFD) * (1.0f / 256.0f));
    }

    // zero-padded input tile (rows y0-10..y0+13, cols -10..57), channel c
    for (int i = tid; i < TROWS * TCOLS; i += TB) {
        int r  = i / TCOLS;
        int xc = i % TCOLS - KR;
        int yy = y0 - KR + r;
        float v = 0.0f;
        if ((unsigned)yy < HW && (unsigned)xc < HW)
            v = in[((n * HW + yy) * HW + xc) * CH + c];
        sp[SP_IN + i] = v;
    }
    __syncthreads();

    // horizontal pass
    for (int i = tid; i < TROWS * HW; i += TB) {
        int r = i / HW, x = i % HW;
        const float* row = sp + SP_IN + r * TCOLS + x;
        float s = 0.0f;
        #pragma unroll
        for (int k = 0; k < KS; k++) s = fmaf(row[k], sp[SP_KG + k], s);
        sp[SP_H + i] = s;
    }
    __syncthreads();

    // vertical pass -> blur value -> linear binning (weights to 2 bins)
    for (int i = tid; i < YT * HW; i += TB) {
        int yo = i / HW, x = i % HW;
        float s = 0.0f;
        #pragma unroll
        for (int k = 0; k < KS; k++)
            s = fmaf(sp[SP_H + (yo + k) * HW + x], sp[SP_KG + k], s);
        float u = s * 256.0f;
        u = fminf(fmaxf(u, 0.0f), (float)(BINS - 2));
        int   j0 = (int)u;
        float w1 = u - (float)j0;
        atomicAdd(&d_W[n * BINS + j0],     1.0f - w1);
        atomicAdd(&d_W[n * BINS + j0 + 1], w1);
        atomicMin(&d_jmin[n], j0);
        atomicMax(&d_jmax[n], j0 + 1);
    }

    gridbar();

    // ---------------- Phase 2: table[t] = (1/NPIX) sum_j W_j T[t-j] --------
    {
        const int n2   = b & 3;
        const int rank = b >> 2;          // 0..35; ranks 0..16 active
        if (rank * 16 < TPTS) {
            const int jmin = d_jmin[n2];
            const int jmax = d_jmax[n2];
            const int Wlen = jmax - jmin + 1;
            const int tlo  = rank * 16;

            for (int i = tid; i < Wlen; i += TB)
                sp[SP2_W + i] = d_W[n2 * BINS + jmin + i];
            const int tbase = tlo - jmax + OFFD;   // >= 0 by construction
            for (int i = tid; i < Wlen + 16; i += TB)
                sp[SP2_T + i] = d_T[tbase + i];
            __syncthreads();

            const int t = tlo + warp;
            if (t < TPTS) {
                const float* sT = sp + SP2_T + (t - tlo) + (jmax - jmin);
                float a0 = 0.f, a1 = 0.f;
                int jj = lane;
                #pragma unroll 2
                for (; jj + 32 < Wlen; jj += 64) {
                    a0 = fmaf(sp[SP2_W + jj],      sT[-jj],      a0);
                    a1 = fmaf(sp[SP2_W + jj + 32], sT[-jj - 32], a1);
                }
                if (jj < Wlen) a0 = fmaf(sp[SP2_W + jj], sT[-jj], a0);
                float s = a0 + a1;
                #pragma unroll
                for (int o = 16; o > 0; o >>= 1)
                    s += __shfl_xor_sync(0xffffffffu, s, o);
                if (lane == 0)
                    d_table[n2 * TPTS + t] = s * (1.0f / (float)NPIX);
            }
        }
    }

    gridbar();

    // ---------------- Phase 3: out = M(inputs) - W(diff); re-arm scratch ---
    // Re-zero histogram + reset range trackers for the next graph replay.
    {
        int i0 = b * 157;                           // 157*144 >= NIMG*BINS
        for (int i = i0 + tid; i < i0 + 157 && i < NIMG * BINS; i += TB)
            d_W[i] = 0.0f;
        if (b < NIMG && tid == 0) { d_jmin[b] = BINS; d_jmax[b] = 0; }
    }

    if (warp == 0)      make_k1d(gm[c], sp + SP_KM);
    else if (warp == 1) make_k1d(gw[c], sp + SP_KW);

    for (int i = tid; i < TPTS; i += TB)
        sp[SP_TBL + i] = d_table[n * TPTS + i];
    __syncthreads();

    // zero-padded (input, diff) tiles; diff = lerp of per-image table at x
    for (int i = tid; i < TROWS * TCOLS; i += TB) {
        int r  = i / TCOLS;
        int xc = i % TCOLS - KR;
        int yy = y0 - KR + r;
        float v = 0.0f, d = 0.0f;
        if ((unsigned)yy < HW && (unsigned)xc < HW) {
            v = in[((n * HW + yy) * HW + xc) * CH + c];
            float u = v * 256.0f;
            u = fminf(fmaxf(u, 0.0f), 255.999f);
            int   i0 = (int)u;
            float fr = u - (float)i0;
            float t0 = sp[SP_TBL + i0], t1 = sp[SP_TBL + i0 + 1];
            d = fmaf(t1 - t0, fr, t0);
        }
        sp[SP_IN + i] = v;
        sp[SP_DF + i] = d;
    }
    __syncthreads();

    // horizontal passes (both convs)
    for (int i = tid; i < TROWS * HW; i += TB) {
        int r = i / HW, x = i % HW;
        const float* rin = sp + SP_IN + r * TCOLS + x;
        const float* rdf = sp + SP_DF + r * TCOLS + x;
        float sm = 0.0f, sw = 0.0f;
        #pragma unroll
        for (int k = 0; k < KS; k++) {
            sm = fmaf(rin[k], sp[SP_KM + k], sm);
            sw = fmaf(rdf[k], sp[SP_KW + k], sw);
        }
        sp[SP_HM + i] = sm;
        sp[SP_HW + i] = sw;
    }
    __syncthreads();

    // vertical passes + final subtraction (L = 1)
    for (int i = tid; i < YT * HW; i += TB) {
        int yo = i / HW, x = i % HW;
        float sm = 0.0f, sw = 0.0f;
        #pragma unroll
        for (int k = 0; k < KS; k++) {
            sm = fmaf(sp[SP_HM + (yo + k) * HW + x], sp[SP_KM + k], sm);
            sw = fmaf(sp[SP_HW + (yo + k) * HW + x], sp[SP_KW + k], sw);
        }
        out[((n * HW + y0 + yo) * HW + x) * CH + c] = sm - sw;
    }
}

extern "C" void kernel_launch(void* const* d_in, const int* in_sizes, int n_in,
                              void* d_out, int out_size) {
    const float* in = (const float*)d_in[0];
    const float* gm = (const float*)d_in[1];
    const float* gw = (const float*)d_in[2];
    const float* gg = (const float*)d_in[3];
    float* out = (float*)d_out;

    inrf_fused<<<GRID, TB>>>(in, gm, gw, gg, out);
}

// round 5
// speedup vs baseline: 1.2581x; 1.1366x over previous
#include <cuda_runtime.h>
#include <math.h>

// Problem constants
#define NIMG   4
#define HW     48
#define CH     3
#define PLANE  (HW*HW)            // 2304
#define NPIX   (PLANE*CH)         // 6912 per image
#define KS     21
#define KR     10

// Config
#define TPTS   257                // x-grid: t/256, t=0..256
#define GRID   144                // 1 block/SM -> all co-resident, safe spin barrier
#define TB     512
#define YT     4                  // output rows per conv tile (144 = 4n*3c*12)
#define TROWS  (YT + KS - 1)      // 24
#define TCOLS  (HW + KS - 1)      // 68

// Histogram config (b-grid step = 1/256, aligned with the x-grid)
#define BINS   5632
#define WCAP   3456               // max staged histogram span (floats)
#define STCAP  3712               // max staged tanh window (floats)

// Scratch (device globals; no allocation). d_W / trackers re-armed in P3.
__device__ float d_W[NIMG * BINS];
__device__ int   d_jmin[NIMG] = {BINS, BINS, BINS, BINS};
__device__ int   d_jmax[NIMG] = {0, 0, 0, 0};
__device__ float d_table[NIMG * TPTS];
__device__ unsigned g_cnt = 0;
__device__ volatile unsigned g_gen = 0;

// Shared pool layout (floats):
//  persist: IN @0 (1632), KG@1632 KM@1656 KW@1680 (21 ea), M @11392 (192)
//  P1: H1 @1728 (1152), H2 @2880 (1152), RED @4096 (32 ints)
//  P2: W @4224 (<=3456), ST @7680 (<=3712) -> ends 11392
//  P3: TBL @1728 (257), DF @2048 (1632), H3 @3712 (1152)
#define SP_IN   0
#define SP_KG   1632
#define SP_KM   1656
#define SP_KW   1680
#define SP_H1   1728
#define SP_H2   2880
#define SP_RED  4096
#define SP_W    4224
#define SP_ST   7680
#define SP_TBL  1728
#define SP_DF   2048
#define SP_H3   3712
#define SP_M    11392
#define POOL    11584             // 46336 B static smem

__device__ __forceinline__ float frcp(float x) {
    float r;
    asm("rcp.approx.f32 %0, %1;" : "=f"(r) : "f"(x));
    return r;
}
__device__ __forceinline__ float fex2(float x) {
    float r;
    asm("ex2.approx.f32 %0, %1;" : "=f"(r) : "f"(x));
    return r;
}
// tanh(z) = 1 - 2/(1 + e^{2z}),  e^{2z} = 2^{2z*log2(e)}
__device__ __forceinline__ float ftanh(float z) {
    float u = fex2(z * 2.8853900817779268f);
    return 1.0f - 2.0f * frcp(1.0f + u);
}

// Grid-wide barrier (monotone generation; all GRID blocks co-resident).
__device__ __forceinline__ void gridbar() {
    __syncthreads();
    __threadfence();
    if (threadIdx.x == 0) {
        unsigned gen = g_gen;
        if (atomicAdd(&g_cnt, 1u) == GRID - 1) {
            g_cnt = 0;
            __threadfence();
            g_gen = gen + 1;
        } else {
            while (g_gen == gen) {}
        }
    }
    __syncthreads();
    __threadfence();
}

// One warp builds a unit-L2 1D Gaussian (2D kernel = exact outer product).
__device__ __forceinline__ void make_k1d(float gamma, float* out) {
    int lane = threadIdx.x & 31;
    float inv2s2 = 0.5f * gamma * gamma;
    const float step = (21.0f / 32.0f) / 20.0f;
    const float mean = 21.0f / 64.0f;
    float v = 0.0f;
    if (lane < KS) {
        float d = (float)lane * step - mean;
        v = expf(-d * d * inv2s2);
    }
    float ss = v * v;
    #pragma unroll
    for (int o = 16; o > 0; o >>= 1) ss += __shfl_xor_sync(0xffffffffu, ss, o);
    if (lane < KS) out[lane] = v * rsqrtf(ss);
}

__global__ __launch_bounds__(TB, 1)
void inrf_fused(const float* __restrict__ in,
                const float* __restrict__ gm,
                const float* __restrict__ gw,
                const float* __restrict__ gg,
                float* __restrict__ out) {
    __shared__ float sp[POOL];

    const int tid  = threadIdx.x;
    const int warp = tid >> 5;
    const int lane = tid & 31;

    // Conv decomposition: 144 = 4n * 3c * 12 ytiles
    const int b   = blockIdx.x;
    const int n   = b / 36;
    const int rem = b % 36;
    const int c   = rem / 12;
    const int y0  = (rem % 12) * YT;

    // ---------------- Phase 1: blur=G(in) -> bin;  M(in) -> smem -----------
    if      (warp == 0) make_k1d(gg[c], sp + SP_KG);
    else if (warp == 1) make_k1d(gm[c], sp + SP_KM);
    else if (warp == 2) make_k1d(gw[c], sp + SP_KW);

    // zero-padded input tile (rows y0-10..y0+13, cols -10..57), channel c
    for (int i = tid; i < TROWS * TCOLS; i += TB) {
        int r  = i / TCOLS;
        int xc = i % TCOLS - KR;
        int yy = y0 - KR + r;
        float v = 0.0f;
        if ((unsigned)yy < HW && (unsigned)xc < HW)
            v = in[((n * HW + yy) * HW + xc) * CH + c];
        sp[SP_IN + i] = v;
    }
    __syncthreads();

    // taps -> registers (warp-uniform broadcasts, once)
    float tg[KS], tm[KS];
    #pragma unroll
    for (int k = 0; k < KS; k++) { tg[k] = sp[SP_KG + k]; tm[k] = sp[SP_KM + k]; }

    // horizontal pass, both convs
    for (int i = tid; i < TROWS * HW; i += TB) {
        int r = i / HW, x = i % HW;
        const float* row = sp + SP_IN + r * TCOLS + x;
        float s1 = 0.0f, s2 = 0.0f;
        #pragma unroll
        for (int k = 0; k < KS; k++) {
            float v = row[k];
            s1 = fmaf(v, tg[k], s1);
            s2 = fmaf(v, tm[k], s2);
        }
        sp[SP_H1 + i] = s1;
        sp[SP_H2 + i] = s2;
    }
    __syncthreads();

    // vertical pass: bin G-blur (linear weights); store M result
    int j0min = BINS, j0max = 0;
    for (int i = tid; i < YT * HW; i += TB) {
        int yo = i / HW, x = i % HW;
        float sg = 0.0f, sm = 0.0f;
        #pragma unroll
        for (int k = 0; k < KS; k++) {
            sg = fmaf(sp[SP_H1 + (yo + k) * HW + x], tg[k], sg);
            sm = fmaf(sp[SP_H2 + (yo + k) * HW + x], tm[k], sm);
        }
        sp[SP_M + i] = sm;
        float u = fminf(fmaxf(sg * 256.0f, 0.0f), (float)(BINS - 2));
        int   j0 = (int)u;
        float w1 = u - (float)j0;
        atomicAdd(&d_W[n * BINS + j0],     1.0f - w1);
        atomicAdd(&d_W[n * BINS + j0 + 1], w1);
        j0min = min(j0min, j0);
        j0max = max(j0max, j0 + 1);
    }
    // block-reduce range trackers -> 1 atomic each per block
    #pragma unroll
    for (int o = 16; o > 0; o >>= 1) {
        j0min = min(j0min, __shfl_xor_sync(0xffffffffu, j0min, o));
        j0max = max(j0max, __shfl_xor_sync(0xffffffffu, j0max, o));
    }
    int* red = (int*)(sp + SP_RED);
    if (lane == 0) { red[warp] = j0min; red[16 + warp] = j0max; }
    __syncthreads();
    if (tid == 0) {
        int mn = BINS, mx = 0;
        #pragma unroll
        for (int w = 0; w < 16; w++) { mn = min(mn, red[w]); mx = max(mx, red[16 + w]); }
        atomicMin(&d_jmin[n], mn);
        atomicMax(&d_jmax[n], mx);
    }

    gridbar();

    // ---------------- Phase 2: table[t] = (1/NPIX) sum_j W_j tanh((t-j)/256)
    {
        const int n2   = b & 3;
        const int rank = b >> 2;          // ranks 0..16 active (17*16 >= 257)
        if (rank * 16 < TPTS) {
            const int jmin = d_jmin[n2];
            const int jmax = min(d_jmax[n2], jmin + WCAP - 1);
            const int Wlen = jmax - jmin + 1;
            const int tlo  = rank * 16;

            for (int i = tid; i < Wlen; i += TB)
                sp[SP_W + i] = d_W[n2 * BINS + jmin + i];
            // tanh window: ST[i] = tanh((tlo - jmax + i)/256), i in [0, Wlen+16)
            for (int i = tid; i < Wlen + 16; i += TB)
                sp[SP_ST + i] = ftanh((float)(tlo - jmax + i) * (1.0f / 256.0f));
            __syncthreads();

            const int t = tlo + warp;
            if (t < TPTS) {
                const float* sT = sp + SP_ST + (t - tlo) + (jmax - jmin);
                float a0 = 0.f, a1 = 0.f;
                int jj = lane;
                #pragma unroll 2
                for (; jj + 32 < Wlen; jj += 64) {
                    a0 = fmaf(sp[SP_W + jj],      sT[-jj],      a0);
                    a1 = fmaf(sp[SP_W + jj + 32], sT[-jj - 32], a1);
                }
                if (jj < Wlen) a0 = fmaf(sp[SP_W + jj], sT[-jj], a0);
                float s = a0 + a1;
                #pragma unroll
                for (int o = 16; o > 0; o >>= 1)
                    s += __shfl_xor_sync(0xffffffffu, s, o);
                if (lane == 0)
                    d_table[n2 * TPTS + t] = s * (1.0f / (float)NPIX);
            }
        }
    }

    gridbar();

    // ---------------- Phase 3: out = M - W(diff); re-arm scratch -----------
    // re-zero histogram slices + reset trackers (next replay)
    {
        int i0 = b * 157;                          // 157*144 >= NIMG*BINS
        for (int i = i0 + tid; i < i0 + 157 && i < NIMG * BINS; i += TB)
            d_W[i] = 0.0f;
        if (b < NIMG && tid == 0) { d_jmin[b] = BINS; d_jmax[b] = 0; }
    }

    for (int i = tid; i < TPTS; i += TB)
        sp[SP_TBL + i] = d_table[n * TPTS + i];
    float tw[KS];
    #pragma unroll
    for (int k = 0; k < KS; k++) tw[k] = sp[SP_KW + k];
    __syncthreads();

    // diff tile from persisted IN tile (zero outside the image)
    for (int i = tid; i < TROWS * TCOLS; i += TB) {
        int r  = i / TCOLS;
        int xc = i % TCOLS - KR;
        int yy = y0 - KR + r;
        float d = 0.0f;
        if ((unsigned)yy < HW && (unsigned)xc < HW) {
            float u = sp[SP_IN + i] * 256.0f;
            u = fminf(fmaxf(u, 0.0f), 255.999f);
            int   i0 = (int)u;
            float fr = u - (float)i0;
            float t0 = sp[SP_TBL + i0], t1 = sp[SP_TBL + i0 + 1];
            d = fmaf(t1 - t0, fr, t0);
        }
        sp[SP_DF + i] = d;
    }
    __syncthreads();

    // horizontal pass (W conv)
    for (int i = tid; i < TROWS * HW; i += TB) {
        int r = i / HW, x = i % HW;
        const float* row = sp + SP_DF + r * TCOLS + x;
        float s = 0.0f;
        #pragma unroll
        for (int k = 0; k < KS; k++) s = fmaf(row[k], tw[k], s);
        sp[SP_H3 + i] = s;
    }
    __syncthreads();

    // vertical pass + final subtraction (L = 1)
    for (int i = tid; i < YT * HW; i += TB) {
        int yo = i / HW, x = i % HW;
        float sw = 0.0f;
        #pragma unroll
        for (int k = 0; k < KS; k++)
            sw = fmaf(sp[SP_H3 + (yo + k) * HW + x], tw[k], sw);
        out[((n * HW + y0 + yo) * HW + x) * CH + c] = sp[SP_M + i] - sw;
    }
}

extern "C" void kernel_launch(void* const* d_in, const int* in_sizes, int n_in,
                              void* d_out, int out_size) {
    const float* in = (const float*)d_in[0];
    const float* gm = (const float*)d_in[1];
    const float* gw = (const float*)d_in[2];
    const float* gg = (const float*)d_in[3];
    float* out = (float*)d_out;

    inrf_fused<<<GRID, TB>>>(in, gm, gw, gg, out);
}